// round 8
// baseline (speedup 1.0000x reference)
#include <cuda_runtime.h>
#include <cstddef>

// Problem constants (fixed by the reference setup_inputs)
#define EPS_F 1e-8f
constexpr int N_NODES = 4096;
constexpr int N_EDGES = 2048;
constexpr int DIN  = 256;
constexpr int DOUT = 256;
constexpr int BATCH = 8;
constexpr int NC = BATCH * DOUT;  // 2048 folded columns (b*256 + d)

// Scratch (device globals — no allocation allowed)
__device__ float g_Xs[N_NODES * NC];   // 32 MB: Dv^{-1/2} (xW^T + b), [node, b*256+d]
__device__ float g_Y [N_EDGES * NC];   // 16 MB: diag(w/de) H^T Xs,   [edge, b*256+d]
__device__ float g_de  [N_EDGES];
__device__ float g_dvis[N_NODES];      // (dv+eps)^{-1/2}
__device__ float g_sce [N_EDGES];      // w/(de+eps)
__device__ float g_Wt  [DIN * DOUT];   // W transposed: Wt[k*DOUT + d]

// ---------------------------------------------------------------------------
// Degree kernels
// ---------------------------------------------------------------------------

// dv[n] = sum_e H[n,e]*w[e]; store rsqrt(dv+eps). One block per node row.
__global__ void dv_kernel(const float* __restrict__ H, const float* __restrict__ w) {
    int n = blockIdx.x;
    const float* row = H + (size_t)n * N_EDGES;
    float s = 0.f;
    #pragma unroll
    for (int e = threadIdx.x; e < N_EDGES; e += 256) s += row[e] * w[e];
    __shared__ float red[256];
    red[threadIdx.x] = s;
    __syncthreads();
    for (int off = 128; off > 0; off >>= 1) {
        if (threadIdx.x < off) red[threadIdx.x] += red[threadIdx.x + off];
        __syncthreads();
    }
    if (threadIdx.x == 0) g_dvis[n] = rsqrtf(red[0] + EPS_F);
}

// de[e] = sum_n H[n,e]. Partial column sums + atomicAdd (exact: integer-valued).
__global__ void de_kernel(const float* __restrict__ H) {
    int e  = blockIdx.x * 256 + threadIdx.x;
    int n0 = blockIdx.y * 128;
    float s = 0.f;
    #pragma unroll 8
    for (int n = n0; n < n0 + 128; ++n) s += H[(size_t)n * N_EDGES + e];
    atomicAdd(&g_de[e], s);
}

__global__ void sce_kernel(const float* __restrict__ w) {
    int e = blockIdx.x * 256 + threadIdx.x;
    g_sce[e] = w[e] / (g_de[e] + EPS_F);
}

// Transpose W[d,k] -> Wt[k,d] so the GEMM B-operand is row-major in n.
__global__ void wt_kernel(const float* __restrict__ W) {
    int idx = blockIdx.x * 256 + threadIdx.x;  // d*256 + k
    int d = idx >> 8, k = idx & 255;
    g_Wt[k * DOUT + d] = W[idx];
}

// ---------------------------------------------------------------------------
// Tiled fp32 GEMM: C = A @ B, 128x128 tile, BK=8, 256 threads, 8x8 per thread.
// TRANSA=false: A[m][k] = A[m*lda + k]   (row-major)
// TRANSA=true : A[m][k] = A[k*lda + m]   (i.e. computes H^T without a copy)
// MODE 0: Linear epilogue  — (acc + bias[n]) * dvis[m&4095], scatter to Xs[j, b*256+d]
// MODE 1: edge epilogue    — acc * sce[m] -> Y[m, n]
// MODE 2: output epilogue  — acc * dvis[m] -> out[b, m, d] with n = b*256+d
// ---------------------------------------------------------------------------
template<int MODE, bool TRANSA>
__global__ void __launch_bounds__(256, 2)
gemm_kernel(const float* __restrict__ A, const float* __restrict__ B,
            float* __restrict__ C, int K, int lda, int ldb,
            const float* __restrict__ rs, const float* __restrict__ bias)
{
    __shared__ float As[2][8][132];   // padded: conflict-free transposed stores
    __shared__ float Bs[2][8][132];

    const int tid = threadIdx.x;
    const int bm = blockIdx.y * 128;
    const int bn = blockIdx.x * 128;

    // Loader indices
    const int lkk = tid >> 5;           // 0..7   (TRANSA A-loader + B-loader)
    const int lmn = (tid & 31) * 4;     // 0..124
    const int lrow = tid >> 1;          // 0..127 (row-major A-loader)
    const int lkq  = (tid & 1) * 4;     // 0 or 4

    // Prologue: tile kt = 0 into buffer 0
    if constexpr (TRANSA) {
        float4 v = *(const float4*)(A + (size_t)lkk * lda + bm + lmn);
        *(float4*)&As[0][lkk][lmn] = v;
    } else {
        float4 v = *(const float4*)(A + (size_t)(bm + lrow) * lda + lkq);
        As[0][lkq + 0][lrow] = v.x;
        As[0][lkq + 1][lrow] = v.y;
        As[0][lkq + 2][lrow] = v.z;
        As[0][lkq + 3][lrow] = v.w;
    }
    {
        float4 v = *(const float4*)(B + (size_t)lkk * ldb + bn + lmn);
        *(float4*)&Bs[0][lkk][lmn] = v;
    }
    __syncthreads();

    float acc[8][8];
    #pragma unroll
    for (int i = 0; i < 8; ++i)
        #pragma unroll
        for (int j = 0; j < 8; ++j) acc[i][j] = 0.f;

    const int tx = tid & 15;   // n direction
    const int ty = tid >> 4;   // m direction
    const int nk = K >> 3;
    int buf = 0;
    float4 ra, rb;

    for (int kt = 0; kt < nk; ++kt) {
        const int k0n = (kt + 1) << 3;
        const bool has = (kt + 1 < nk);
        if (has) {
            if constexpr (TRANSA) {
                ra = *(const float4*)(A + (size_t)(k0n + lkk) * lda + bm + lmn);
            } else {
                ra = *(const float4*)(A + (size_t)(bm + lrow) * lda + k0n + lkq);
            }
            rb = *(const float4*)(B + (size_t)(k0n + lkk) * ldb + bn + lmn);
        }

        #pragma unroll
        for (int kk = 0; kk < 8; ++kk) {
            float a[8], b[8];
            float4 t;
            t = *(float4*)&As[buf][kk][ty * 4];       a[0]=t.x; a[1]=t.y; a[2]=t.z; a[3]=t.w;
            t = *(float4*)&As[buf][kk][64 + ty * 4];  a[4]=t.x; a[5]=t.y; a[6]=t.z; a[7]=t.w;
            t = *(float4*)&Bs[buf][kk][tx * 4];       b[0]=t.x; b[1]=t.y; b[2]=t.z; b[3]=t.w;
            t = *(float4*)&Bs[buf][kk][64 + tx * 4];  b[4]=t.x; b[5]=t.y; b[6]=t.z; b[7]=t.w;
            #pragma unroll
            for (int i = 0; i < 8; ++i)
                #pragma unroll
                for (int j = 0; j < 8; ++j)
                    acc[i][j] = fmaf(a[i], b[j], acc[i][j]);
        }

        if (has) {
            const int nb = buf ^ 1;
            if constexpr (TRANSA) {
                *(float4*)&As[nb][lkk][lmn] = ra;
            } else {
                As[nb][lkq + 0][lrow] = ra.x;
                As[nb][lkq + 1][lrow] = ra.y;
                As[nb][lkq + 2][lrow] = ra.z;
                As[nb][lkq + 3][lrow] = ra.w;
            }
            *(float4*)&Bs[nb][lkk][lmn] = rb;
            __syncthreads();
            buf = nb;
        }
    }

    // Epilogue
    #pragma unroll
    for (int i = 0; i < 8; ++i) {
        const int m = bm + ((i < 4) ? (ty * 4 + i) : (64 + ty * 4 + i - 4));
        float s;
        if constexpr (MODE == 0) s = rs[m & (N_NODES - 1)];
        else                     s = rs[m];

        #pragma unroll
        for (int h = 0; h < 2; ++h) {
            const int n0 = bn + h * 64 + tx * 4;
            float4 v;
            if constexpr (MODE == 0) {
                const float4 bb = *(const float4*)(bias + n0);
                v.x = (acc[i][h*4+0] + bb.x) * s;
                v.y = (acc[i][h*4+1] + bb.y) * s;
                v.z = (acc[i][h*4+2] + bb.z) * s;
                v.w = (acc[i][h*4+3] + bb.w) * s;
                const int j  = m & (N_NODES - 1);
                const int bt = m >> 12;
                *(float4*)(C + (size_t)j * NC + bt * DOUT + n0) = v;
            } else if constexpr (MODE == 1) {
                v.x = acc[i][h*4+0] * s;
                v.y = acc[i][h*4+1] * s;
                v.z = acc[i][h*4+2] * s;
                v.w = acc[i][h*4+3] * s;
                *(float4*)(C + (size_t)m * NC + n0) = v;
            } else {
                v.x = acc[i][h*4+0] * s;
                v.y = acc[i][h*4+1] * s;
                v.z = acc[i][h*4+2] * s;
                v.w = acc[i][h*4+3] * s;
                const int bt = n0 >> 8;     // batch
                const int d  = n0 & 255;    // head dim
                *(float4*)(C + ((size_t)bt * N_NODES + m) * DOUT + d) = v;
            }
        }
    }
}

// ---------------------------------------------------------------------------
// Launch
// ---------------------------------------------------------------------------
extern "C" void kernel_launch(void* const* d_in, const int* in_sizes, int n_in,
                              void* d_out, int out_size)
{
    const float* x    = (const float*)d_in[0];  // [8, 4096, 256]
    const float* w    = (const float*)d_in[1];  // [2048]
    const float* H    = (const float*)d_in[2];  // [4096, 2048]
    const float* W    = (const float*)d_in[3];  // [256, 256]
    const float* bias = (const float*)d_in[4];  // [256]
    float* out = (float*)d_out;                 // [8, 4096, 256]

    float *Xs, *Y, *de, *dvis, *sce, *Wt;
    cudaGetSymbolAddress((void**)&Xs,   g_Xs);
    cudaGetSymbolAddress((void**)&Y,    g_Y);
    cudaGetSymbolAddress((void**)&de,   g_de);
    cudaGetSymbolAddress((void**)&dvis, g_dvis);
    cudaGetSymbolAddress((void**)&sce,  g_sce);
    cudaGetSymbolAddress((void**)&Wt,   g_Wt);

    // Degrees + diagonal scales
    cudaMemsetAsync(de, 0, N_EDGES * sizeof(float));
    dv_kernel<<<N_NODES, 256>>>(H, w);
    de_kernel<<<dim3(N_EDGES / 256, 32), 256>>>(H);
    sce_kernel<<<N_EDGES / 256, 256>>>(w);
    wt_kernel<<<(DIN * DOUT) / 256, 256>>>(W);

    // Stage 1: Xs[j, b*256+d] = dvis[j]*(x[b,j,:]@W[d,:] + bias[d])
    //   GEMM: [32768, 256] = x_flat[32768,256] @ Wt[256,256]
    gemm_kernel<0, false><<<dim3(DOUT / 128, (BATCH * N_NODES) / 128), 256>>>(
        x, Wt, Xs, DIN, DIN, DOUT, dvis, bias);

    // Stage 2: Y = diag(w/de) * (H^T @ Xs)  — [2048, 2048], K = 4096
    gemm_kernel<1, true><<<dim3(NC / 128, N_EDGES / 128), 256>>>(
        H, Xs, Y, N_NODES, N_EDGES, NC, sce, nullptr);

    // Stage 3: out[b,n,d] = dvis[n] * (H @ Y)[n, b*256+d]  — [4096, 2048], K = 2048
    gemm_kernel<2, false><<<dim3(NC / 128, N_NODES / 128), 256>>>(
        H, Y, out, N_EDGES, N_EDGES, NC, dvis, nullptr);

    (void)in_sizes; (void)n_in; (void)out_size;
}

// round 9
// speedup vs baseline: 1.0573x; 1.0573x over previous
#include <cuda_runtime.h>
#include <cstddef>

// Problem constants (fixed by the reference setup_inputs)
#define EPS_F 1e-8f
constexpr int N_NODES = 4096;
constexpr int N_EDGES = 2048;
constexpr int DIN  = 256;
constexpr int DOUT = 256;
constexpr int BATCH = 8;
constexpr int NC = BATCH * DOUT;  // 2048 folded columns (b*256 + d)

// Scratch (device globals — no allocation allowed)
__device__ float g_Xs[N_NODES * NC];   // 32 MB: Dv^{-1/2} (xW^T + b), [node, b*256+d]
__device__ float g_Y [N_EDGES * NC];   // 16 MB: diag(w/de) H^T Xs,   [edge, b*256+d]
__device__ float g_de  [N_EDGES];
__device__ float g_dvis[N_NODES];      // (dv+eps)^{-1/2}
__device__ float g_sce [N_EDGES];      // w/(de+eps)
__device__ float g_Wt  [DIN * DOUT];   // W transposed: Wt[k*DOUT + d]

// ---------------------------------------------------------------------------
// Degree kernels
// ---------------------------------------------------------------------------

// dv[n] = sum_e H[n,e]*w[e]; store rsqrt(dv+eps). One block per node row.
__global__ void dv_kernel(const float* __restrict__ H, const float* __restrict__ w) {
    int n = blockIdx.x;
    const float* row = H + (size_t)n * N_EDGES;
    float s = 0.f;
    #pragma unroll
    for (int e = threadIdx.x; e < N_EDGES; e += 256) s += row[e] * w[e];
    __shared__ float red[256];
    red[threadIdx.x] = s;
    __syncthreads();
    for (int off = 128; off > 0; off >>= 1) {
        if (threadIdx.x < off) red[threadIdx.x] += red[threadIdx.x + off];
        __syncthreads();
    }
    if (threadIdx.x == 0) g_dvis[n] = rsqrtf(red[0] + EPS_F);
}

// de[e] = sum_n H[n,e]. Partial column sums + atomicAdd (exact: integer-valued).
__global__ void de_kernel(const float* __restrict__ H) {
    int e  = blockIdx.x * 256 + threadIdx.x;
    int n0 = blockIdx.y * 128;
    float s = 0.f;
    #pragma unroll 8
    for (int n = n0; n < n0 + 128; ++n) s += H[(size_t)n * N_EDGES + e];
    atomicAdd(&g_de[e], s);
}

__global__ void sce_kernel(const float* __restrict__ w) {
    int e = blockIdx.x * 256 + threadIdx.x;
    g_sce[e] = w[e] / (g_de[e] + EPS_F);
}

// Transpose W[d,k] -> Wt[k,d] so the GEMM B-operand is row-major in n.
__global__ void wt_kernel(const float* __restrict__ W) {
    int idx = blockIdx.x * 256 + threadIdx.x;  // d*256 + k
    int d = idx >> 8, k = idx & 255;
    g_Wt[k * DOUT + d] = W[idx];
}

// ---------------------------------------------------------------------------
// Tiled fp32 GEMM: C = A @ B, 128x128 tile, BK=8, 256 threads, 8x8 per thread.
// TRANSA=false: A[m][k] = A[m*lda + k]   (row-major)
// TRANSA=true : A[m][k] = A[k*lda + m]   (i.e. computes H^T without a copy)
// MODE 0: Linear epilogue  — (acc + bias[n]) * dvis[m&4095], scatter to Xs[j, b*256+d]
// MODE 1: edge epilogue    — acc * sce[m] -> Y[m, n]
// MODE 2: output epilogue  — acc * dvis[m] -> out[b, m, d] with n = b*256+d
// ---------------------------------------------------------------------------
template<int MODE, bool TRANSA>
__global__ void __launch_bounds__(256, 2)
gemm_kernel(const float* __restrict__ A, const float* __restrict__ B,
            float* __restrict__ C, int K, int lda, int ldb,
            const float* __restrict__ rs, const float* __restrict__ bias)
{
    __shared__ float As[2][8][132];   // padded: conflict-free transposed stores
    __shared__ float Bs[2][8][132];

    const int tid = threadIdx.x;
    const int bm = blockIdx.y * 128;
    const int bn = blockIdx.x * 128;

    // Loader indices
    const int lkk = tid >> 5;           // 0..7   (TRANSA A-loader + B-loader)
    const int lmn = (tid & 31) * 4;     // 0..124
    const int lrow = tid >> 1;          // 0..127 (row-major A-loader)
    const int lkq  = (tid & 1) * 4;     // 0 or 4

    // Prologue: tile kt = 0 into buffer 0
    if constexpr (TRANSA) {
        float4 v = *(const float4*)(A + (size_t)lkk * lda + bm + lmn);
        *(float4*)&As[0][lkk][lmn] = v;
    } else {
        float4 v = *(const float4*)(A + (size_t)(bm + lrow) * lda + lkq);
        As[0][lkq + 0][lrow] = v.x;
        As[0][lkq + 1][lrow] = v.y;
        As[0][lkq + 2][lrow] = v.z;
        As[0][lkq + 3][lrow] = v.w;
    }
    {
        float4 v = *(const float4*)(B + (size_t)lkk * ldb + bn + lmn);
        *(float4*)&Bs[0][lkk][lmn] = v;
    }
    __syncthreads();

    float acc[8][8];
    #pragma unroll
    for (int i = 0; i < 8; ++i)
        #pragma unroll
        for (int j = 0; j < 8; ++j) acc[i][j] = 0.f;

    const int tx = tid & 15;   // n direction
    const int ty = tid >> 4;   // m direction
    const int nk = K >> 3;
    int buf = 0;
    float4 ra, rb;

    for (int kt = 0; kt < nk; ++kt) {
        const int k0n = (kt + 1) << 3;
        const bool has = (kt + 1 < nk);
        if (has) {
            if constexpr (TRANSA) {
                ra = *(const float4*)(A + (size_t)(k0n + lkk) * lda + bm + lmn);
            } else {
                ra = *(const float4*)(A + (size_t)(bm + lrow) * lda + k0n + lkq);
            }
            rb = *(const float4*)(B + (size_t)(k0n + lkk) * ldb + bn + lmn);
        }

        #pragma unroll
        for (int kk = 0; kk < 8; ++kk) {
            float a[8], b[8];
            float4 t;
            t = *(float4*)&As[buf][kk][ty * 4];       a[0]=t.x; a[1]=t.y; a[2]=t.z; a[3]=t.w;
            t = *(float4*)&As[buf][kk][64 + ty * 4];  a[4]=t.x; a[5]=t.y; a[6]=t.z; a[7]=t.w;
            t = *(float4*)&Bs[buf][kk][tx * 4];       b[0]=t.x; b[1]=t.y; b[2]=t.z; b[3]=t.w;
            t = *(float4*)&Bs[buf][kk][64 + tx * 4];  b[4]=t.x; b[5]=t.y; b[6]=t.z; b[7]=t.w;
            #pragma unroll
            for (int i = 0; i < 8; ++i)
                #pragma unroll
                for (int j = 0; j < 8; ++j)
                    acc[i][j] = fmaf(a[i], b[j], acc[i][j]);
        }

        if (has) {
            const int nb = buf ^ 1;
            if constexpr (TRANSA) {
                *(float4*)&As[nb][lkk][lmn] = ra;
            } else {
                As[nb][lkq + 0][lrow] = ra.x;
                As[nb][lkq + 1][lrow] = ra.y;
                As[nb][lkq + 2][lrow] = ra.z;
                As[nb][lkq + 3][lrow] = ra.w;
            }
            *(float4*)&Bs[nb][lkk][lmn] = rb;
            __syncthreads();
            buf = nb;
        }
    }

    // Epilogue
    #pragma unroll
    for (int i = 0; i < 8; ++i) {
        const int m = bm + ((i < 4) ? (ty * 4 + i) : (64 + ty * 4 + i - 4));
        float s;
        if constexpr (MODE == 0) s = rs[m & (N_NODES - 1)];
        else                     s = rs[m];

        #pragma unroll
        for (int h = 0; h < 2; ++h) {
            const int n0 = bn + h * 64 + tx * 4;
            float4 v;
            if constexpr (MODE == 0) {
                const float4 bb = *(const float4*)(bias + n0);
                v.x = (acc[i][h*4+0] + bb.x) * s;
                v.y = (acc[i][h*4+1] + bb.y) * s;
                v.z = (acc[i][h*4+2] + bb.z) * s;
                v.w = (acc[i][h*4+3] + bb.w) * s;
                const int j  = m & (N_NODES - 1);
                const int bt = m >> 12;
                *(float4*)(C + (size_t)j * NC + bt * DOUT + n0) = v;
            } else if constexpr (MODE == 1) {
                v.x = acc[i][h*4+0] * s;
                v.y = acc[i][h*4+1] * s;
                v.z = acc[i][h*4+2] * s;
                v.w = acc[i][h*4+3] * s;
                *(float4*)(C + (size_t)m * NC + n0) = v;
            } else {
                v.x = acc[i][h*4+0] * s;
                v.y = acc[i][h*4+1] * s;
                v.z = acc[i][h*4+2] * s;
                v.w = acc[i][h*4+3] * s;
                const int bt = n0 >> 8;     // batch
                const int d  = n0 & 255;    // head dim
                *(float4*)(C + ((size_t)bt * N_NODES + m) * DOUT + d) = v;
            }
        }
    }
}

// ---------------------------------------------------------------------------
// Launch
// ---------------------------------------------------------------------------
extern "C" void kernel_launch(void* const* d_in, const int* in_sizes, int n_in,
                              void* d_out, int out_size)
{
    const float* x    = (const float*)d_in[0];  // [8, 4096, 256]
    const float* w    = (const float*)d_in[1];  // [2048]
    const float* H    = (const float*)d_in[2];  // [4096, 2048]
    const float* W    = (const float*)d_in[3];  // [256, 256]
    const float* bias = (const float*)d_in[4];  // [256]
    float* out = (float*)d_out;                 // [8, 4096, 256]

    float *Xs, *Y, *de, *dvis, *sce, *Wt;
    cudaGetSymbolAddress((void**)&Xs,   g_Xs);
    cudaGetSymbolAddress((void**)&Y,    g_Y);
    cudaGetSymbolAddress((void**)&de,   g_de);
    cudaGetSymbolAddress((void**)&dvis, g_dvis);
    cudaGetSymbolAddress((void**)&sce,  g_sce);
    cudaGetSymbolAddress((void**)&Wt,   g_Wt);

    // Degrees + diagonal scales
    cudaMemsetAsync(de, 0, N_EDGES * sizeof(float));
    dv_kernel<<<N_NODES, 256>>>(H, w);
    de_kernel<<<dim3(N_EDGES / 256, 32), 256>>>(H);
    sce_kernel<<<N_EDGES / 256, 256>>>(w);
    wt_kernel<<<(DIN * DOUT) / 256, 256>>>(W);

    // Stage 1: Xs[j, b*256+d] = dvis[j]*(x[b,j,:]@W[d,:] + bias[d])
    //   GEMM: [32768, 256] = x_flat[32768,256] @ Wt[256,256]
    gemm_kernel<0, false><<<dim3(DOUT / 128, (BATCH * N_NODES) / 128), 256>>>(
        x, Wt, Xs, DIN, DIN, DOUT, dvis, bias);

    // Stage 2: Y = diag(w/de) * (H^T @ Xs)  — [2048, 2048], K = 4096
    gemm_kernel<1, true><<<dim3(NC / 128, N_EDGES / 128), 256>>>(
        H, Xs, Y, N_NODES, N_EDGES, NC, sce, nullptr);

    // Stage 3: out[b,n,d] = dvis[n] * (H @ Y)[n, b*256+d]  — [4096, 2048], K = 2048
    gemm_kernel<2, false><<<dim3(NC / 128, N_NODES / 128), 256>>>(
        H, Y, out, N_EDGES, N_EDGES, NC, dvis, nullptr);

    (void)in_sizes; (void)n_in; (void)out_size;
}